// round 3
// baseline (speedup 1.0000x reference)
#include <cuda_runtime.h>
#include <cuda_bf16.h>

// Problem constants (fixed per dataset metadata)
#define NN 100000          // num nodes
#define DD 64              // signature dim

// ---------------- scratch (device globals: allocation-free) ----------------
__device__ float g_xw  [NN * DD];   // x * node_weight
__device__ float g_one [NN * DD];   // one_hop
__device__ float g_two [NN * DD];   // two_iter
__device__ float g_deg [NN];
__device__ float g_deg2[NN];
__device__ int   g_rowptr[NN + 1];

// ---------------- kernel 1: xw = x * w ----------------
__global__ void xw_kernel(const float* __restrict__ x,
                          const float* __restrict__ w,
                          int n_elems4) {
    int i = blockIdx.x * blockDim.x + threadIdx.x;
    if (i >= n_elems4) return;
    float4 v = ((const float4*)x)[i];
    float ww = __ldg(&w[i >> 4]);           // 16 float4 per 64-wide row
    v.x *= ww; v.y *= ww; v.z *= ww; v.w *= ww;
    ((float4*)g_xw)[i] = v;
}

// ---------------- kernel 2: CSR row_ptr (binary search, sorted adj_row) + deg ----
__global__ void rowptr_kernel(const int* __restrict__ adj_row, int nadj, int n) {
    int r = blockIdx.x * blockDim.x + threadIdx.x;
    if (r > n) return;
    int lo = 0, hi = nadj;
    while (lo < hi) {
        int mid = (lo + hi) >> 1;
        if (__ldg(&adj_row[mid]) < r) lo = mid + 1; else hi = mid;
    }
    g_rowptr[r] = lo;
    if (r < n) {
        int lo2 = lo, hi2 = nadj;
        while (lo2 < hi2) {
            int mid = (lo2 + hi2) >> 1;
            if (__ldg(&adj_row[mid]) < r + 1) lo2 = mid + 1; else hi2 = mid;
        }
        g_deg[r] = (float)(lo2 - lo);
    }
}

// ---------------- SpMM body (atomic-free segment sum via CSR) ----------------
// One 64-thread CTA per destination node; thread = feature dim.
// Device-inlined so the entry kernels can bind the device globals in DEVICE code.
template <bool WITH_DEG2>
__device__ __forceinline__ void spmm_body(const float* __restrict__ src,
                                          float*       __restrict__ dst,
                                          const int*   __restrict__ adj_col) {
    const int r = blockIdx.x;
    const int t = threadIdx.x;               // 0..63
    const int start = g_rowptr[r];
    const int end   = g_rowptr[r + 1];

    __shared__ int   scols[64];
    __shared__ float sred[64];

    float acc0 = 0.f, acc1 = 0.f, acc2 = 0.f, acc3 = 0.f;
    float dsum = 0.f;

    for (int base = start; base < end; base += 64) {
        int chunk = min(64, end - base);
        __syncthreads();
        if (t < chunk) {
            int c = __ldg(&adj_col[base + t]);
            scols[t] = c;
            if (WITH_DEG2) dsum += g_deg[c];
        }
        __syncthreads();
        int j = 0;
        for (; j + 4 <= chunk; j += 4) {
            int c0 = scols[j],     c1 = scols[j + 1];
            int c2 = scols[j + 2], c3 = scols[j + 3];
            acc0 += __ldg(&src[c0 * DD + t]);
            acc1 += __ldg(&src[c1 * DD + t]);
            acc2 += __ldg(&src[c2 * DD + t]);
            acc3 += __ldg(&src[c3 * DD + t]);
        }
        for (; j < chunk; ++j)
            acc0 += __ldg(&src[scols[j] * DD + t]);
    }
    dst[r * DD + t] = (acc0 + acc1) + (acc2 + acc3);

    if (WITH_DEG2) {
        sred[t] = dsum;
        __syncthreads();
        if (t < 32) {
            float v = sred[t] + sred[t + 32];
            #pragma unroll
            for (int o = 16; o > 0; o >>= 1)
                v += __shfl_down_sync(0xffffffffu, v, o);
            if (t == 0)
                g_deg2[r] = fmaxf(v - g_deg[r] - 1.0f, 0.0f);
        }
    }
}

// Concrete entry points: device globals bound INSIDE device code (correct
// addresses). Host never touches a __device__ symbol.
__global__ void spmm_one_kernel(const int* __restrict__ adj_col) {
    spmm_body<true>(g_xw, g_one, adj_col);    // one_hop + deg2
}
__global__ void spmm_two_kernel(const int* __restrict__ adj_col) {
    spmm_body<false>(g_one, g_two, adj_col);  // two_iter
}

// ---------------- kernel 5: per-query-edge features (1 warp / edge) ----------
__global__ void edge_kernel(const int* __restrict__ edges, int ne,
                            float* __restrict__ out) {
    int gw   = (blockIdx.x * blockDim.x + threadIdx.x) >> 5;
    int lane = threadIdx.x & 31;
    if (gw >= ne) return;

    const int u = __ldg(&edges[gw]);
    const int v = __ldg(&edges[ne + gw]);

    float2 xu = ((const float2*)(g_xw  + u * DD))[lane];
    float2 xv = ((const float2*)(g_xw  + v * DD))[lane];
    float2 u1 = ((const float2*)(g_one + u * DD))[lane];
    float2 v1 = ((const float2*)(g_one + v * DD))[lane];
    float2 tu = ((const float2*)(g_two + u * DD))[lane];
    float2 tv = ((const float2*)(g_two + v * DD))[lane];

    const float du  = g_deg [u], dv  = g_deg [v];
    const float du2 = g_deg2[u], dv2 = g_deg2[v];

    // two_hop rows recomputed in registers (never materialized)
    float2 u2, v2, au, av;
    u2.x = tu.x - u1.x - xu.x;  u2.y = tu.y - u1.y - xu.y;
    v2.x = tv.x - v1.x - xv.x;  v2.y = tv.y - v1.y - xv.y;
    au.x = tu.x - du * xu.x;    au.y = tu.y - du * xu.y;
    av.x = tv.x - dv * xv.x;    av.y = tv.y - dv * xv.y;

    float c11  = u1.x * v1.x + u1.y * v1.y;
    float c12  = u1.x * v2.x + u1.y * v2.y;
    float c21  = u2.x * v1.x + u2.y * v1.y;
    float c22  = u2.x * v2.x + u2.y * v2.y;
    float cb12 = u1.x * tv.x + u1.y * tv.y;
    float cb21 = tu.x * v1.x + tu.y * v1.y;
    float cb22 = au.x * av.x + au.y * av.y;
    float cs12 = u1.x * tu.x + u1.y * tu.y;
    float cs21 = v1.x * tv.x + v1.y * tv.y;

    #pragma unroll
    for (int o = 16; o > 0; o >>= 1) {
        c11  += __shfl_down_sync(0xffffffffu, c11,  o);
        c12  += __shfl_down_sync(0xffffffffu, c12,  o);
        c21  += __shfl_down_sync(0xffffffffu, c21,  o);
        c22  += __shfl_down_sync(0xffffffffu, c22,  o);
        cb12 += __shfl_down_sync(0xffffffffu, cb12, o);
        cb21 += __shfl_down_sync(0xffffffffu, cb21, o);
        cb22 += __shfl_down_sync(0xffffffffu, cb22, o);
        cs12 += __shfl_down_sync(0xffffffffu, cs12, o);
        cs21 += __shfl_down_sync(0xffffffffu, cs21, o);
    }

    if (lane == 0) {
        float c1inf = du  + dv  - 2.0f * c11 - c12 - c21;
        float c2inf = du2 + dv2 - 2.0f * c22 - c12 - c21;
        float* o15 = out + (size_t)gw * 15;
        o15[0]  = c11;   o15[1]  = c12;  o15[2]  = c21;  o15[3]  = c22;
        o15[4]  = c1inf; o15[5]  = c2inf;
        o15[6]  = cb12;  o15[7]  = cb21; o15[8]  = cb22;
        o15[9]  = cs12;  o15[10] = cs21;
        o15[11] = du;    o15[12] = dv;   o15[13] = du2;  o15[14] = dv2;
    }
}

// ---------------- launch (pure kernel launches: graph-capturable) ----------
extern "C" void kernel_launch(void* const* d_in, const int* in_sizes, int n_in,
                              void* d_out, int out_size) {
    const float* x  = (const float*)d_in[0];
    const float* w  = (const float*)d_in[1];
    const int*   ed = (const int*)  d_in[2];
    const int*   ar = (const int*)  d_in[3];
    const int*   ac = (const int*)  d_in[4];

    const int n    = in_sizes[1];            // 100000
    const int ne   = in_sizes[2] / 2;        // 262144
    const int nadj = in_sizes[3];            // 1600000

    // 1) xw = x * node_weight
    {
        int n4 = (n * DD) / 4;
        xw_kernel<<<(n4 + 255) / 256, 256>>>(x, w, n4);
    }
    // 2) CSR rowptr + deg
    rowptr_kernel<<<(n + 1 + 255) / 256, 256>>>(ar, nadj, n);
    // 3) one_hop = A @ xw   (also deg2)
    spmm_one_kernel<<<n, 64>>>(ac);
    // 4) two_iter = A @ one_hop
    spmm_two_kernel<<<n, 64>>>(ac);
    // 5) per-edge features
    {
        int warps_per_block = 8;                   // 256 threads
        int blocks = (ne + warps_per_block - 1) / warps_per_block;
        edge_kernel<<<blocks, warps_per_block * 32>>>(ed, ne, (float*)d_out);
    }
}

// round 4
// speedup vs baseline: 1.2525x; 1.2525x over previous
#include <cuda_runtime.h>
#include <cuda_bf16.h>

#define NN 100000          // num nodes
#define DD 64              // signature dim

// ---------------- scratch (device globals: allocation-free) ----------------
__device__ float g_xw  [NN * DD];   // x * node_weight
__device__ float g_one [NN * DD];   // one_hop
__device__ float g_two [NN * DD];   // two_iter
__device__ float g_deg [NN];
__device__ float g_deg2[NN];
__device__ int   g_rowptr[NN + 1];

// ---------------- kernel 1: xw = x * w ----------------
__global__ void xw_kernel(const float* __restrict__ x,
                          const float* __restrict__ w,
                          int n_elems4) {
    int i = blockIdx.x * blockDim.x + threadIdx.x;
    if (i >= n_elems4) return;
    float4 v = ((const float4*)x)[i];
    float ww = __ldg(&w[i >> 4]);           // 16 float4 per 64-wide row
    v.x *= ww; v.y *= ww; v.z *= ww; v.w *= ww;
    ((float4*)g_xw)[i] = v;
}

// ---------------- kernel 2: CSR row_ptr (binary search, sorted adj_row) + deg ----
__global__ void rowptr_kernel(const int* __restrict__ adj_row, int nadj, int n) {
    int r = blockIdx.x * blockDim.x + threadIdx.x;
    if (r > n) return;
    int lo = 0, hi = nadj;
    while (lo < hi) {
        int mid = (lo + hi) >> 1;
        if (__ldg(&adj_row[mid]) < r) lo = mid + 1; else hi = mid;
    }
    g_rowptr[r] = lo;
    if (r < n) {
        int lo2 = lo, hi2 = nadj;
        while (lo2 < hi2) {
            int mid = (lo2 + hi2) >> 1;
            if (__ldg(&adj_row[mid]) < r + 1) lo2 = mid + 1; else hi2 = mid;
        }
        g_deg[r] = (float)(lo2 - lo);
    }
}

// ---------------- SpMM: warp-per-node, lane = 2 dims (float2) ----------------
// No shared memory, no barriers. Column indices broadcast via shfl.
template <bool WITH_DEG2>
__device__ __forceinline__ void spmm_warp_body(const float2* __restrict__ src2,
                                               float2*       __restrict__ dst2,
                                               const int*    __restrict__ adj_col,
                                               int n) {
    const int gwarp = (blockIdx.x * blockDim.x + threadIdx.x) >> 5;
    const int lane  = threadIdx.x & 31;
    if (gwarp >= n) return;
    const int r     = gwarp;
    const int start = g_rowptr[r];
    const int end   = g_rowptr[r + 1];

    float2 a0 = {0.f, 0.f}, a1 = {0.f, 0.f}, a2 = {0.f, 0.f}, a3 = {0.f, 0.f};
    float dsum = 0.f;

    for (int base = start; base < end; base += 32) {
        const int chunk = min(32, end - base);
        int c = 0;
        if (lane < chunk) {
            c = __ldg(&adj_col[base + lane]);
            if (WITH_DEG2) dsum += __ldg(&g_deg[c]);
        }
        int j = 0;
        for (; j + 4 <= chunk; j += 4) {
            int c0 = __shfl_sync(0xffffffffu, c, j);
            int c1 = __shfl_sync(0xffffffffu, c, j + 1);
            int c2 = __shfl_sync(0xffffffffu, c, j + 2);
            int c3 = __shfl_sync(0xffffffffu, c, j + 3);
            float2 v0 = __ldg(&src2[c0 * 32 + lane]);
            float2 v1 = __ldg(&src2[c1 * 32 + lane]);
            float2 v2 = __ldg(&src2[c2 * 32 + lane]);
            float2 v3 = __ldg(&src2[c3 * 32 + lane]);
            a0.x += v0.x; a0.y += v0.y;
            a1.x += v1.x; a1.y += v1.y;
            a2.x += v2.x; a2.y += v2.y;
            a3.x += v3.x; a3.y += v3.y;
        }
        for (; j < chunk; ++j) {
            int cj = __shfl_sync(0xffffffffu, c, j);
            float2 v = __ldg(&src2[cj * 32 + lane]);
            a0.x += v.x; a0.y += v.y;
        }
    }
    float2 res;
    res.x = (a0.x + a1.x) + (a2.x + a3.x);
    res.y = (a0.y + a1.y) + (a2.y + a3.y);
    dst2[r * 32 + lane] = res;

    if (WITH_DEG2) {
        #pragma unroll
        for (int o = 16; o > 0; o >>= 1)
            dsum += __shfl_xor_sync(0xffffffffu, dsum, o);
        if (lane == 0)
            g_deg2[r] = fmaxf(dsum - g_deg[r] - 1.0f, 0.0f);
    }
}

__global__ void spmm_one_kernel(const int* __restrict__ adj_col, int n) {
    spmm_warp_body<true>((const float2*)g_xw, (float2*)g_one, adj_col, n);
}
__global__ void spmm_two_kernel(const int* __restrict__ adj_col, int n) {
    spmm_warp_body<false>((const float2*)g_one, (float2*)g_two, adj_col, n);
}

// ---------------- edge features: half-warp per edge, lane = 4 dims (float4) ----
__device__ __forceinline__ float dot4(float4 a, float4 b) {
    return a.x * b.x + a.y * b.y + a.z * b.z + a.w * b.w;
}

__global__ void edge_kernel(const int* __restrict__ edges, int ne,
                            float* __restrict__ out) {
    const int ghw  = (blockIdx.x * blockDim.x + threadIdx.x) >> 4;  // half-warp id
    const int l    = threadIdx.x & 15;                              // 0..15
    if (ghw >= ne) return;

    const int u = __ldg(&edges[ghw]);
    const int v = __ldg(&edges[ne + ghw]);

    const float4* xu_p = (const float4*)(g_xw  + u * DD);
    const float4* xv_p = (const float4*)(g_xw  + v * DD);
    const float4* u1_p = (const float4*)(g_one + u * DD);
    const float4* v1_p = (const float4*)(g_one + v * DD);
    const float4* tu_p = (const float4*)(g_two + u * DD);
    const float4* tv_p = (const float4*)(g_two + v * DD);

    float4 xu = __ldg(&xu_p[l]), xv = __ldg(&xv_p[l]);
    float4 u1 = __ldg(&u1_p[l]), v1 = __ldg(&v1_p[l]);
    float4 tu = __ldg(&tu_p[l]), tv = __ldg(&tv_p[l]);

    const float du  = __ldg(&g_deg [u]), dv  = __ldg(&g_deg [v]);
    const float du2 = __ldg(&g_deg2[u]), dv2 = __ldg(&g_deg2[v]);

    // two_hop rows in registers (never materialized)
    float4 u2, v2, au, av;
    u2.x = tu.x - u1.x - xu.x; u2.y = tu.y - u1.y - xu.y;
    u2.z = tu.z - u1.z - xu.z; u2.w = tu.w - u1.w - xu.w;
    v2.x = tv.x - v1.x - xv.x; v2.y = tv.y - v1.y - xv.y;
    v2.z = tv.z - v1.z - xv.z; v2.w = tv.w - v1.w - xv.w;
    au.x = tu.x - du * xu.x;   au.y = tu.y - du * xu.y;
    au.z = tu.z - du * xu.z;   au.w = tu.w - du * xu.w;
    av.x = tv.x - dv * xv.x;   av.y = tv.y - dv * xv.y;
    av.z = tv.z - dv * xv.z;   av.w = tv.w - dv * xv.w;

    float c11  = dot4(u1, v1);
    float c12  = dot4(u1, v2);
    float c21  = dot4(u2, v1);
    float c22  = dot4(u2, v2);
    float cb12 = dot4(u1, tv);
    float cb21 = dot4(tu, v1);
    float cb22 = dot4(au, av);
    float cs12 = dot4(u1, tu);
    float cs21 = dot4(v1, tv);

    // butterfly within the 16-lane group (masks 8,4,2,1 stay inside the group)
    #pragma unroll
    for (int o = 8; o > 0; o >>= 1) {
        c11  += __shfl_xor_sync(0xffffffffu, c11,  o);
        c12  += __shfl_xor_sync(0xffffffffu, c12,  o);
        c21  += __shfl_xor_sync(0xffffffffu, c21,  o);
        c22  += __shfl_xor_sync(0xffffffffu, c22,  o);
        cb12 += __shfl_xor_sync(0xffffffffu, cb12, o);
        cb21 += __shfl_xor_sync(0xffffffffu, cb21, o);
        cb22 += __shfl_xor_sync(0xffffffffu, cb22, o);
        cs12 += __shfl_xor_sync(0xffffffffu, cs12, o);
        cs21 += __shfl_xor_sync(0xffffffffu, cs21, o);
    }

    if (l == 0) {
        float c1inf = du  + dv  - 2.0f * c11 - c12 - c21;
        float c2inf = du2 + dv2 - 2.0f * c22 - c12 - c21;
        float* o15 = out + (size_t)ghw * 15;
        o15[0]  = c11;   o15[1]  = c12;  o15[2]  = c21;  o15[3]  = c22;
        o15[4]  = c1inf; o15[5]  = c2inf;
        o15[6]  = cb12;  o15[7]  = cb21; o15[8]  = cb22;
        o15[9]  = cs12;  o15[10] = cs21;
        o15[11] = du;    o15[12] = dv;   o15[13] = du2;  o15[14] = dv2;
    }
}

// ---------------- launch (pure kernel launches: graph-capturable) ----------
extern "C" void kernel_launch(void* const* d_in, const int* in_sizes, int n_in,
                              void* d_out, int out_size) {
    const float* x  = (const float*)d_in[0];
    const float* w  = (const float*)d_in[1];
    const int*   ed = (const int*)  d_in[2];
    const int*   ar = (const int*)  d_in[3];
    const int*   ac = (const int*)  d_in[4];

    const int n    = in_sizes[1];            // 100000
    const int ne   = in_sizes[2] / 2;        // 262144
    const int nadj = in_sizes[3];            // 1600000

    // 1) xw = x * node_weight
    {
        int n4 = (n * DD) / 4;
        xw_kernel<<<(n4 + 255) / 256, 256>>>(x, w, n4);
    }
    // 2) CSR rowptr + deg
    rowptr_kernel<<<(n + 1 + 255) / 256, 256>>>(ar, nadj, n);
    // 3) one_hop = A @ xw   (+ deg2); warp per node, 8 warps/block
    {
        int blocks = (n + 7) / 8;
        spmm_one_kernel<<<blocks, 256>>>(ac, n);
    }
    // 4) two_iter = A @ one_hop
    {
        int blocks = (n + 7) / 8;
        spmm_two_kernel<<<blocks, 256>>>(ac, n);
    }
    // 5) per-edge features; half-warp per edge, 16 edges / 256-thread block
    {
        int blocks = (ne + 15) / 16;
        edge_kernel<<<blocks, 256>>>(ed, ne, (float*)d_out);
    }
}

// round 6
// speedup vs baseline: 1.4381x; 1.1482x over previous
#include <cuda_runtime.h>
#include <cuda_bf16.h>

#define NN 100000          // num nodes
#define DD 64              // signature dim

// ---------------- scratch (device globals: allocation-free) ----------------
__device__ float g_xw  [NN * DD];   // x * node_weight
__device__ float g_one [NN * DD];   // one_hop
__device__ float g_two [NN * DD];   // two_iter
__device__ float g_deg [NN];
__device__ float g_deg2[NN];
__device__ int   g_rowptr[NN + 1];

// ---------------- kernel 1: xw = x * w ----------------
__global__ void xw_kernel(const float* __restrict__ x,
                          const float* __restrict__ w,
                          int n_elems4) {
    int i = blockIdx.x * blockDim.x + threadIdx.x;
    if (i >= n_elems4) return;
    float4 v = ((const float4*)x)[i];
    float ww = __ldg(&w[i >> 4]);           // 16 float4 per 64-wide row
    v.x *= ww; v.y *= ww; v.z *= ww; v.w *= ww;
    ((float4*)g_xw)[i] = v;
}

// ---------------- kernel 2: CSR row_ptr (binary search, sorted adj_row) + deg ----
__global__ void rowptr_kernel(const int* __restrict__ adj_row, int nadj, int n) {
    int r = blockIdx.x * blockDim.x + threadIdx.x;
    if (r > n) return;
    int lo = 0, hi = nadj;
    while (lo < hi) {
        int mid = (lo + hi) >> 1;
        if (__ldg(&adj_row[mid]) < r) lo = mid + 1; else hi = mid;
    }
    g_rowptr[r] = lo;
    if (r < n) {
        int lo2 = lo, hi2 = nadj;
        while (lo2 < hi2) {
            int mid = (lo2 + hi2) >> 1;
            if (__ldg(&adj_row[mid]) < r + 1) lo2 = mid + 1; else hi2 = mid;
        }
        g_deg[r] = (float)(lo2 - lo);
    }
}

// ---------------- SpMM: 16-lane subwarp per node, lane = 4 dims (float4) -----
// One LDG.128 x 16 lanes = full 256B row per gather. 2 nodes per warp.
// CRITICAL: shuffles inside the (data-dependently divergent) chunk loop use
// the exact 16-lane subwarp mask, never the full-warp mask.
template <bool WITH_DEG2>
__device__ __forceinline__ void spmm_sub_body(const float4* __restrict__ src4,
                                              float4*       __restrict__ dst4,
                                              const int*    __restrict__ adj_col,
                                              int n) {
    const int tid  = blockIdx.x * blockDim.x + threadIdx.x;
    const int node = tid >> 4;
    const int lane = threadIdx.x & 15;     // 0..15 within subwarp
    if (node >= n) return;

    // member mask of THIS 16-lane subwarp within its warp
    const unsigned smask = 0xffffu << (threadIdx.x & 16);

    const int start = g_rowptr[node];
    const int end   = g_rowptr[node + 1];

    float4 a0 = {0,0,0,0}, a1 = {0,0,0,0}, a2 = {0,0,0,0}, a3 = {0,0,0,0};
    float dsum = 0.f;

    for (int base = start; base < end; base += 16) {
        const int chunk = min(16, end - base);
        int c = 0;
        if (lane < chunk) {
            c = __ldg(&adj_col[base + lane]);
            if (WITH_DEG2) dsum += __ldg(&g_deg[c]);
        }
        int j = 0;
        for (; j + 4 <= chunk; j += 4) {
            int c0 = __shfl_sync(smask, c, j,     16);
            int c1 = __shfl_sync(smask, c, j + 1, 16);
            int c2 = __shfl_sync(smask, c, j + 2, 16);
            int c3 = __shfl_sync(smask, c, j + 3, 16);
            float4 v0 = __ldg(&src4[c0 * 16 + lane]);
            float4 v1 = __ldg(&src4[c1 * 16 + lane]);
            float4 v2 = __ldg(&src4[c2 * 16 + lane]);
            float4 v3 = __ldg(&src4[c3 * 16 + lane]);
            a0.x += v0.x; a0.y += v0.y; a0.z += v0.z; a0.w += v0.w;
            a1.x += v1.x; a1.y += v1.y; a1.z += v1.z; a1.w += v1.w;
            a2.x += v2.x; a2.y += v2.y; a2.z += v2.z; a2.w += v2.w;
            a3.x += v3.x; a3.y += v3.y; a3.z += v3.z; a3.w += v3.w;
        }
        for (; j < chunk; ++j) {
            int cj = __shfl_sync(smask, c, j, 16);
            float4 v = __ldg(&src4[cj * 16 + lane]);
            a0.x += v.x; a0.y += v.y; a0.z += v.z; a0.w += v.w;
        }
    }
    float4 res;
    res.x = (a0.x + a1.x) + (a2.x + a3.x);
    res.y = (a0.y + a1.y) + (a2.y + a3.y);
    res.z = (a0.z + a1.z) + (a2.z + a3.z);
    res.w = (a0.w + a1.w) + (a2.w + a3.w);
    dst4[node * 16 + lane] = res;

    if (WITH_DEG2) {
        #pragma unroll
        for (int o = 8; o > 0; o >>= 1)
            dsum += __shfl_xor_sync(smask, dsum, o, 16);
        if (lane == 0)
            g_deg2[node] = fmaxf(dsum - g_deg[node] - 1.0f, 0.0f);
    }
}

__global__ void spmm_one_kernel(const int* __restrict__ adj_col, int n) {
    spmm_sub_body<true>((const float4*)g_xw, (float4*)g_one, adj_col, n);
}
__global__ void spmm_two_kernel(const int* __restrict__ adj_col, int n) {
    spmm_sub_body<false>((const float4*)g_one, (float4*)g_two, adj_col, n);
}

// ---------------- edge features: 8-lane subwarp per edge, 2x float4/lane -----
__device__ __forceinline__ float dot4(float4 a, float4 b) {
    return a.x * b.x + a.y * b.y + a.z * b.z + a.w * b.w;
}
__device__ __forceinline__ float4 sub3(float4 t, float4 o, float4 x) {
    float4 r; r.x = t.x - o.x - x.x; r.y = t.y - o.y - x.y;
    r.z = t.z - o.z - x.z; r.w = t.w - o.w - x.w; return r;
}
__device__ __forceinline__ float4 fnma(float4 t, float d, float4 x) {
    float4 r; r.x = t.x - d * x.x; r.y = t.y - d * x.y;
    r.z = t.z - d * x.z; r.w = t.w - d * x.w; return r;
}

__global__ void edge_kernel(const int* __restrict__ edges, int ne,
                            float* __restrict__ out) {
    const int ge = (blockIdx.x * blockDim.x + threadIdx.x) >> 3;  // edge id
    const int l  = threadIdx.x & 7;                               // 0..7
    if (ge >= ne) return;

    // member mask of THIS 8-lane subwarp
    const unsigned emask = 0xffu << (threadIdx.x & 24);

    const int u = __ldg(&edges[ge]);
    const int v = __ldg(&edges[ne + ge]);

    const float4* xu_p = (const float4*)(g_xw  + u * DD);
    const float4* xv_p = (const float4*)(g_xw  + v * DD);
    const float4* u1_p = (const float4*)(g_one + u * DD);
    const float4* v1_p = (const float4*)(g_one + v * DD);
    const float4* tu_p = (const float4*)(g_two + u * DD);
    const float4* tv_p = (const float4*)(g_two + v * DD);

    // each lane covers dims [l*4, l*4+4) and [(l+8)*4, (l+8)*4+4)
    float4 xuA = __ldg(&xu_p[l]), xuB = __ldg(&xu_p[l + 8]);
    float4 xvA = __ldg(&xv_p[l]), xvB = __ldg(&xv_p[l + 8]);
    float4 u1A = __ldg(&u1_p[l]), u1B = __ldg(&u1_p[l + 8]);
    float4 v1A = __ldg(&v1_p[l]), v1B = __ldg(&v1_p[l + 8]);
    float4 tuA = __ldg(&tu_p[l]), tuB = __ldg(&tu_p[l + 8]);
    float4 tvA = __ldg(&tv_p[l]), tvB = __ldg(&tv_p[l + 8]);

    const float du  = __ldg(&g_deg [u]), dv  = __ldg(&g_deg [v]);
    const float du2 = __ldg(&g_deg2[u]), dv2 = __ldg(&g_deg2[v]);

    float4 u2A = sub3(tuA, u1A, xuA), u2B = sub3(tuB, u1B, xuB);
    float4 v2A = sub3(tvA, v1A, xvA), v2B = sub3(tvB, v1B, xvB);
    float4 auA = fnma(tuA, du, xuA),  auB = fnma(tuB, du, xuB);
    float4 avA = fnma(tvA, dv, xvA),  avB = fnma(tvB, dv, xvB);

    float c11  = dot4(u1A, v1A) + dot4(u1B, v1B);
    float c12  = dot4(u1A, v2A) + dot4(u1B, v2B);
    float c21  = dot4(u2A, v1A) + dot4(u2B, v1B);
    float c22  = dot4(u2A, v2A) + dot4(u2B, v2B);
    float cb12 = dot4(u1A, tvA) + dot4(u1B, tvB);
    float cb21 = dot4(tuA, v1A) + dot4(tuB, v1B);
    float cb22 = dot4(auA, avA) + dot4(auB, avB);
    float cs12 = dot4(u1A, tuA) + dot4(u1B, tuB);
    float cs21 = dot4(v1A, tvA) + dot4(v1B, tvB);

    // butterfly within the 8-lane group
    #pragma unroll
    for (int o = 4; o > 0; o >>= 1) {
        c11  += __shfl_xor_sync(emask, c11,  o, 8);
        c12  += __shfl_xor_sync(emask, c12,  o, 8);
        c21  += __shfl_xor_sync(emask, c21,  o, 8);
        c22  += __shfl_xor_sync(emask, c22,  o, 8);
        cb12 += __shfl_xor_sync(emask, cb12, o, 8);
        cb21 += __shfl_xor_sync(emask, cb21, o, 8);
        cb22 += __shfl_xor_sync(emask, cb22, o, 8);
        cs12 += __shfl_xor_sync(emask, cs12, o, 8);
        cs21 += __shfl_xor_sync(emask, cs21, o, 8);
    }

    if (l == 0) {
        float c1inf = du  + dv  - 2.0f * c11 - c12 - c21;
        float c2inf = du2 + dv2 - 2.0f * c22 - c12 - c21;
        float* o15 = out + (size_t)ge * 15;
        o15[0]  = c11;   o15[1]  = c12;  o15[2]  = c21;  o15[3]  = c22;
        o15[4]  = c1inf; o15[5]  = c2inf;
        o15[6]  = cb12;  o15[7]  = cb21; o15[8]  = cb22;
        o15[9]  = cs12;  o15[10] = cs21;
        o15[11] = du;    o15[12] = dv;   o15[13] = du2;  o15[14] = dv2;
    }
}

// ---------------- launch (pure kernel launches: graph-capturable) ----------
extern "C" void kernel_launch(void* const* d_in, const int* in_sizes, int n_in,
                              void* d_out, int out_size) {
    const float* x  = (const float*)d_in[0];
    const float* w  = (const float*)d_in[1];
    const int*   ed = (const int*)  d_in[2];
    const int*   ar = (const int*)  d_in[3];
    const int*   ac = (const int*)  d_in[4];

    const int n    = in_sizes[1];            // 100000
    const int ne   = in_sizes[2] / 2;        // 262144
    const int nadj = in_sizes[3];            // 1600000

    // 1) xw = x * node_weight
    {
        int n4 = (n * DD) / 4;
        xw_kernel<<<(n4 + 255) / 256, 256>>>(x, w, n4);
    }
    // 2) CSR rowptr + deg
    rowptr_kernel<<<(n + 1 + 255) / 256, 256>>>(ar, nadj, n);
    // 3) one_hop = A @ xw (+ deg2); 16 lanes/node -> 16 nodes per 256-thr block
    {
        int blocks = (n + 15) / 16;
        spmm_one_kernel<<<blocks, 256>>>(ac, n);
    }
    // 4) two_iter = A @ one_hop
    {
        int blocks = (n + 15) / 16;
        spmm_two_kernel<<<blocks, 256>>>(ac, n);
    }
    // 5) per-edge features; 8 lanes/edge -> 32 edges per 256-thr block
    {
        int blocks = (ne + 31) / 32;
        edge_kernel<<<blocks, 256>>>(ed, ne, (float*)d_out);
    }
}